// round 1
// baseline (speedup 1.0000x reference)
#include <cuda_runtime.h>
#include <cstdint>
#include <math.h>

#define B_   16
#define N_   2048
#define FIN  256
#define H_   128
#define NEG_INF_F (-9000000000000000.0f)

// Scratch (allocation-free: __device__ globals)
__device__ float g_wh[B_ * N_ * H_];     // 16.8 MB
__device__ float g_src[B_ * N_];         // src + b_a folded in
__device__ float g_dst[B_ * N_];

// ---------------------------------------------------------------------------
// Kernel A: wh[r][h] = sum_f inputs[r][f] * W[h][f] + b_W[h]
// 128x128 output tile per block, K-tile 32, 256 threads, 8x8 microtile.
// ---------------------------------------------------------------------------
__global__ __launch_bounds__(256) void k_proj(const float* __restrict__ inp,
                                              const float* __restrict__ W,
                                              const float* __restrict__ bW) {
    __shared__ __align__(16) float A_s[32 * 132];
    __shared__ __align__(16) float W_s[32 * 132];
    int t = threadIdx.x;
    int row0 = blockIdx.x * 128;
    int tr = t >> 4, tc = t & 15;

    float acc[8][8];
#pragma unroll
    for (int i = 0; i < 8; i++)
#pragma unroll
        for (int j = 0; j < 8; j++) acc[i][j] = 0.f;

    for (int k0 = 0; k0 < FIN; k0 += 32) {
#pragma unroll
        for (int v = 0; v < 4; v++) {
            int f4 = t + 256 * v;
            int r = f4 >> 3;
            int c = (f4 & 7) * 4;
            float4 a = *(const float4*)(inp + (size_t)(row0 + r) * FIN + k0 + c);
            A_s[(c + 0) * 132 + r] = a.x;
            A_s[(c + 1) * 132 + r] = a.y;
            A_s[(c + 2) * 132 + r] = a.z;
            A_s[(c + 3) * 132 + r] = a.w;
            float4 b = *(const float4*)(W + (size_t)r * FIN + k0 + c);
            W_s[(c + 0) * 132 + r] = b.x;
            W_s[(c + 1) * 132 + r] = b.y;
            W_s[(c + 2) * 132 + r] = b.z;
            W_s[(c + 3) * 132 + r] = b.w;
        }
        __syncthreads();
#pragma unroll
        for (int kk = 0; kk < 32; kk++) {
            float a[8], b[8];
            *(float4*)&a[0] = *(const float4*)&A_s[kk * 132 + tr * 8];
            *(float4*)&a[4] = *(const float4*)&A_s[kk * 132 + tr * 8 + 4];
            *(float4*)&b[0] = *(const float4*)&W_s[kk * 132 + tc * 8];
            *(float4*)&b[4] = *(const float4*)&W_s[kk * 132 + tc * 8 + 4];
#pragma unroll
            for (int i = 0; i < 8; i++)
#pragma unroll
                for (int j = 0; j < 8; j++)
                    acc[i][j] = fmaf(a[i], b[j], acc[i][j]);
        }
        __syncthreads();
    }

#pragma unroll
    for (int i = 0; i < 8; i++) {
        int r = row0 + tr * 8 + i;
#pragma unroll
        for (int j = 0; j < 8; j += 4) {
            int h = tc * 8 + j;
            float4 o;
            o.x = acc[i][j + 0] + bW[h + 0];
            o.y = acc[i][j + 1] + bW[h + 1];
            o.z = acc[i][j + 2] + bW[h + 2];
            o.w = acc[i][j + 3] + bW[h + 3];
            *(float4*)(g_wh + (size_t)r * H_ + h) = o;
        }
    }
}

// ---------------------------------------------------------------------------
// Kernel B: src[r] = wh[r]·a1 + b_a ; dst[r] = wh[r]·a2.  One warp per row.
// ---------------------------------------------------------------------------
__global__ __launch_bounds__(256) void k_srcdst(const float* __restrict__ a,
                                                const float* __restrict__ b_a) {
    int row = blockIdx.x * 8 + (threadIdx.x >> 5);
    int lane = threadIdx.x & 31;
    float4 wv = *(const float4*)(g_wh + (size_t)row * H_ + lane * 4);
    float4 a1 = *(const float4*)(a + lane * 4);
    float4 a2 = *(const float4*)(a + H_ + lane * 4);
    float s1 = wv.x * a1.x + wv.y * a1.y + wv.z * a1.z + wv.w * a1.w;
    float s2 = wv.x * a2.x + wv.y * a2.y + wv.z * a2.z + wv.w * a2.w;
#pragma unroll
    for (int o = 16; o; o >>= 1) {
        s1 += __shfl_xor_sync(~0u, s1, o);
        s2 += __shfl_xor_sync(~0u, s2, o);
    }
    if (lane == 0) {
        g_src[row] = s1 + b_a[0];
        g_dst[row] = s2;
    }
}

// ---------------------------------------------------------------------------
// Kernel C: fused masked-softmax attention + ELU.
// Block: 64 i-rows of one batch. 256 threads: thread = (ti = t>>2, q = t&3).
// Quad (4 threads, same warp) owns one i-row; each thread owns 32 h-columns
// with interleaved mapping h = k*16 + q*4 + c (conflict-free smem reads).
// j-tiles of 64; adj read directly from gmem (int4, perfectly sectored).
// PV uses packed fma.rn.f32x2 (FFMA2) on ulonglong2 accumulator pairs.
// ---------------------------------------------------------------------------
__global__ __launch_bounds__(256, 2) void k_attn(const int* __restrict__ adj,
                                                 float* __restrict__ out) {
    __shared__ __align__(16) float wh_s[64 * 128];
    __shared__ __align__(16) float dst_s[64];

    int t = threadIdx.x;
    int ti = t >> 2, q = t & 3;
    int lane = t & 31;
    int qbase = lane & ~3;
    int b = blockIdx.y;
    int i = blockIdx.x * 64 + ti;

    float my_src = g_src[b * N_ + i];
    float m = NEG_INF_F, l = 0.f;
    unsigned long long acc2[16];
#pragma unroll
    for (int u = 0; u < 16; u++) acc2[u] = 0ull;

    const int* adj_row = adj + ((size_t)b * N_ + i) * (size_t)N_;

    for (int j0 = 0; j0 < N_; j0 += 64) {
        __syncthreads();   // previous tile's PV reads done
        {
            const float4* s4 = (const float4*)(g_wh + ((size_t)b * N_ + j0) * H_);
            float4* d4 = (float4*)wh_s;
#pragma unroll
            for (int v = 0; v < 8; v++) d4[t + 256 * v] = s4[t + 256 * v];
            if (t < 16)
                *(float4*)(dst_s + t * 4) = *(const float4*)(g_dst + b * N_ + j0 + t * 4);
        }
        __syncthreads();

        // --- score phase: this thread's 16 j's = [q*16, q*16+16) ---
        float e[16];
        const int4* a4 = (const int4*)(adj_row + j0 + q * 16);
#pragma unroll
        for (int v = 0; v < 4; v++) {
            int4 av = a4[v];
            int jj = v * 4;
            float s;
            s = my_src + dst_s[q * 16 + jj + 0]; s = s > 0.f ? s : 0.01f * s; e[jj + 0] = av.x > 0 ? s : NEG_INF_F;
            s = my_src + dst_s[q * 16 + jj + 1]; s = s > 0.f ? s : 0.01f * s; e[jj + 1] = av.y > 0 ? s : NEG_INF_F;
            s = my_src + dst_s[q * 16 + jj + 2]; s = s > 0.f ? s : 0.01f * s; e[jj + 2] = av.z > 0 ? s : NEG_INF_F;
            s = my_src + dst_s[q * 16 + jj + 3]; s = s > 0.f ? s : 0.01f * s; e[jj + 3] = av.w > 0 ? s : NEG_INF_F;
        }
        float tm = NEG_INF_F;
#pragma unroll
        for (int jj = 0; jj < 16; jj++) tm = fmaxf(tm, e[jj]);
        tm = fmaxf(tm, __shfl_xor_sync(~0u, tm, 1));
        tm = fmaxf(tm, __shfl_xor_sync(~0u, tm, 2));

        float m_new = fmaxf(m, tm);
        float scale = __expf(m - m_new);
        l *= scale;
        unsigned long long sc2;
        asm("mov.b64 %0, {%1, %1};" : "=l"(sc2) : "f"(scale));
#pragma unroll
        for (int u = 0; u < 16; u++)
            asm("mul.rn.f32x2 %0, %0, %1;" : "+l"(acc2[u]) : "l"(sc2));

        float p[16], sp = 0.f;
#pragma unroll
        for (int jj = 0; jj < 16; jj++) { p[jj] = __expf(e[jj] - m_new); sp += p[jj]; }
        sp += __shfl_xor_sync(~0u, sp, 1);
        sp += __shfl_xor_sync(~0u, sp, 2);
        l += sp;
        m = m_new;

        // --- PV: acc[h] += p_j * wh[j][h], quad exchanges p via shfl ---
#pragma unroll
        for (int q2 = 0; q2 < 4; q2++) {
#pragma unroll
            for (int jj = 0; jj < 16; jj++) {
                float pj = __shfl_sync(~0u, p[jj], qbase + q2);
                unsigned long long pj2;
                asm("mov.b64 %0, {%1, %1};" : "=l"(pj2) : "f"(pj));
                int j = q2 * 16 + jj;
                const ulonglong2* wrow = (const ulonglong2*)(wh_s + j * 128);
#pragma unroll
                for (int k = 0; k < 8; k++) {
                    ulonglong2 w = wrow[k * 4 + q];   // h = k*16 + q*4 .. +3
                    asm("fma.rn.f32x2 %0, %1, %2, %0;" : "+l"(acc2[k * 2 + 0]) : "l"(w.x), "l"(pj2));
                    asm("fma.rn.f32x2 %0, %1, %2, %0;" : "+l"(acc2[k * 2 + 1]) : "l"(w.y), "l"(pj2));
                }
            }
        }
    }

    // --- epilogue: normalize, ELU, store ---
    float inv = 1.0f / l;
    float* orow = out + ((size_t)b * N_ + i) * H_;
#pragma unroll
    for (int k = 0; k < 8; k++) {
        float v0, v1, v2, v3;
        asm("mov.b64 {%0, %1}, %2;" : "=f"(v0), "=f"(v1) : "l"(acc2[k * 2 + 0]));
        asm("mov.b64 {%0, %1}, %2;" : "=f"(v2), "=f"(v3) : "l"(acc2[k * 2 + 1]));
        float4 o;
        float x;
        x = v0 * inv; o.x = x > 0.f ? x : expm1f(x);
        x = v1 * inv; o.y = x > 0.f ? x : expm1f(x);
        x = v2 * inv; o.z = x > 0.f ? x : expm1f(x);
        x = v3 * inv; o.w = x > 0.f ? x : expm1f(x);
        *(float4*)(orow + k * 16 + q * 4) = o;
    }
}

// ---------------------------------------------------------------------------
extern "C" void kernel_launch(void* const* d_in, const int* in_sizes, int n_in,
                              void* d_out, int out_size) {
    const float* inputs = (const float*)d_in[0];
    const int*   adj    = (const int*)d_in[1];
    const float* W      = (const float*)d_in[2];
    const float* bW     = (const float*)d_in[3];
    const float* a      = (const float*)d_in[4];
    const float* b_a    = (const float*)d_in[5];
    float* out = (float*)d_out;

    k_proj<<<(B_ * N_) / 128, 256>>>(inputs, W, bW);
    k_srcdst<<<(B_ * N_) / 8, 256>>>(a, b_a);
    k_attn<<<dim3(N_ / 64, B_), 256>>>(adj, out);
}

// round 2
// speedup vs baseline: 1.4181x; 1.4181x over previous
#include <cuda_runtime.h>
#include <cstdint>
#include <math.h>

#define B_   16
#define N_   2048
#define FIN  256
#define H_   128
#define NEG_INF_F (-9000000000000000.0f)

typedef unsigned long long ull;

// Scratch (allocation-free: __device__ globals)
__device__ float g_wh[B_ * N_ * H_];     // 16.8 MB
__device__ float g_src[B_ * N_];         // src + b_a folded in
__device__ float g_dst[B_ * N_];

// ---------------------------------------------------------------------------
// Kernel A: wh[r][h] = sum_f inputs[r][f] * W[h][f] + b_W[h]
// ---------------------------------------------------------------------------
__global__ __launch_bounds__(256) void k_proj(const float* __restrict__ inp,
                                              const float* __restrict__ W,
                                              const float* __restrict__ bW) {
    __shared__ __align__(16) float A_s[32 * 132];
    __shared__ __align__(16) float W_s[32 * 132];
    int t = threadIdx.x;
    int row0 = blockIdx.x * 128;
    int tr = t >> 4, tc = t & 15;

    float acc[8][8];
#pragma unroll
    for (int i = 0; i < 8; i++)
#pragma unroll
        for (int j = 0; j < 8; j++) acc[i][j] = 0.f;

    for (int k0 = 0; k0 < FIN; k0 += 32) {
#pragma unroll
        for (int v = 0; v < 4; v++) {
            int f4 = t + 256 * v;
            int r = f4 >> 3;
            int c = (f4 & 7) * 4;
            float4 a = *(const float4*)(inp + (size_t)(row0 + r) * FIN + k0 + c);
            A_s[(c + 0) * 132 + r] = a.x;
            A_s[(c + 1) * 132 + r] = a.y;
            A_s[(c + 2) * 132 + r] = a.z;
            A_s[(c + 3) * 132 + r] = a.w;
            float4 b = *(const float4*)(W + (size_t)r * FIN + k0 + c);
            W_s[(c + 0) * 132 + r] = b.x;
            W_s[(c + 1) * 132 + r] = b.y;
            W_s[(c + 2) * 132 + r] = b.z;
            W_s[(c + 3) * 132 + r] = b.w;
        }
        __syncthreads();
#pragma unroll
        for (int kk = 0; kk < 32; kk++) {
            float a[8], b[8];
            *(float4*)&a[0] = *(const float4*)&A_s[kk * 132 + tr * 8];
            *(float4*)&a[4] = *(const float4*)&A_s[kk * 132 + tr * 8 + 4];
            *(float4*)&b[0] = *(const float4*)&W_s[kk * 132 + tc * 8];
            *(float4*)&b[4] = *(const float4*)&W_s[kk * 132 + tc * 8 + 4];
#pragma unroll
            for (int i = 0; i < 8; i++)
#pragma unroll
                for (int j = 0; j < 8; j++)
                    acc[i][j] = fmaf(a[i], b[j], acc[i][j]);
        }
        __syncthreads();
    }

#pragma unroll
    for (int i = 0; i < 8; i++) {
        int r = row0 + tr * 8 + i;
#pragma unroll
        for (int j = 0; j < 8; j += 4) {
            int h = tc * 8 + j;
            float4 o;
            o.x = acc[i][j + 0] + bW[h + 0];
            o.y = acc[i][j + 1] + bW[h + 1];
            o.z = acc[i][j + 2] + bW[h + 2];
            o.w = acc[i][j + 3] + bW[h + 3];
            *(float4*)(g_wh + (size_t)r * H_ + h) = o;
        }
    }
}

// ---------------------------------------------------------------------------
// Kernel B: src[r] = wh[r]·a1 + b_a ; dst[r] = wh[r]·a2.
// ---------------------------------------------------------------------------
__global__ __launch_bounds__(256) void k_srcdst(const float* __restrict__ a,
                                                const float* __restrict__ b_a) {
    int row = blockIdx.x * 8 + (threadIdx.x >> 5);
    int lane = threadIdx.x & 31;
    float4 wv = *(const float4*)(g_wh + (size_t)row * H_ + lane * 4);
    float4 a1 = *(const float4*)(a + lane * 4);
    float4 a2 = *(const float4*)(a + H_ + lane * 4);
    float s1 = wv.x * a1.x + wv.y * a1.y + wv.z * a1.z + wv.w * a1.w;
    float s2 = wv.x * a2.x + wv.y * a2.y + wv.z * a2.z + wv.w * a2.w;
#pragma unroll
    for (int o = 16; o; o >>= 1) {
        s1 += __shfl_xor_sync(~0u, s1, o);
        s2 += __shfl_xor_sync(~0u, s2, o);
    }
    if (lane == 0) {
        g_src[row] = s1 + b_a[0];
        g_dst[row] = s2;
    }
}

// ---------------------------------------------------------------------------
// Kernel C: fused masked-softmax attention + ELU.
//
// Block = 64 i-rows of one batch, 256 threads, j-tiles of 64.
// Phase 1 (score): thread (ti=t>>2, q=t&3) computes 16 scores for row ti,
//   does the online-softmax m/l update in quad registers, and writes
//   p duplicated as {p,p} u64 into smem P[64 k][64 i].
// Phase 2 (PV): thread (i_grp=t>>4, h_grp=t&15) owns a 4x8 microtile.
//   Per k: 2 LDS.128 (p-pairs for 4 rows) + 2 LDS.128 (wh pairs for 8 h)
//   + 16 fma.rn.f32x2.  No shfl in the hot loop.
// ---------------------------------------------------------------------------
#define SMEM_WH    0
#define SMEM_P2    (64 * 128 * 4)                 // 32768
#define SMEM_SCALE (SMEM_P2 + 64 * 64 * 8)        // 65536
#define SMEM_L     (SMEM_SCALE + 256)             // 65792
#define SMEM_TOTAL (SMEM_L + 256)                 // 66048

#define FMA2(acc, w, p) asm("fma.rn.f32x2 %0, %1, %2, %0;" : "+l"(acc) : "l"(w), "l"(p))
#define MUL2(acc, s)    asm("mul.rn.f32x2 %0, %0, %1;" : "+l"(acc) : "l"(s))
#define PACK2(d, f)     asm("mov.b64 %0, {%1, %1};" : "=l"(d) : "f"(f))

__global__ __launch_bounds__(256, 2) void k_attn(const int* __restrict__ adj,
                                                 float* __restrict__ out) {
    extern __shared__ __align__(16) char smem_raw[];
    float* wh_s    = (float*)(smem_raw + SMEM_WH);    // [64][128]
    ull*   p2_s    = (ull*)  (smem_raw + SMEM_P2);    // [64 k][64 i], {p,p}
    float* scale_s = (float*)(smem_raw + SMEM_SCALE); // [64]
    float* l_s     = (float*)(smem_raw + SMEM_L);     // [64]

    int t = threadIdx.x;
    // score mapping
    int ti = t >> 2, q = t & 3;
    // PV mapping
    int i_grp = t >> 4, h_grp = t & 15;
    int i0 = i_grp * 4, h0 = h_grp * 8;

    int b = blockIdx.y;
    int row_i = blockIdx.x * 64 + ti;

    float my_src = g_src[b * N_ + row_i];
    float m = NEG_INF_F, l = 0.f;

    ull acc2[16];   // [r 0..3][c 0..3]  (h = h0 + 2c, +1)
#pragma unroll
    for (int u = 0; u < 16; u++) acc2[u] = 0ull;

    const int*   adj_row = adj + ((size_t)b * N_ + row_i) * (size_t)N_;
    const float* dst_row = g_dst + b * N_;

    for (int j0 = 0; j0 < N_; j0 += 64) {
        __syncthreads();   // previous tile's PV reads of wh_s/p2_s done

        // ---- stage wh tile [64][128] ----
        {
            const float4* s4 = (const float4*)(g_wh + ((size_t)b * N_ + j0) * H_);
            float4* d4 = (float4*)wh_s;
#pragma unroll
            for (int v = 0; v < 8; v++) d4[t + 256 * v] = s4[t + 256 * v];
        }

        // ---- score phase: 16 j's = [j0 + q*16, +16) for row ti ----
        float e[16];
        {
            const int4*   a4 = (const int4*)(adj_row + j0 + q * 16);
            const float4* d4 = (const float4*)(dst_row + j0 + q * 16);
#pragma unroll
            for (int v = 0; v < 4; v++) {
                int4 av = a4[v];
                float4 dv = d4[v];
                int jj = v * 4;
                float s;
                s = my_src + dv.x; s = s > 0.f ? s : 0.01f * s; e[jj + 0] = av.x > 0 ? s : NEG_INF_F;
                s = my_src + dv.y; s = s > 0.f ? s : 0.01f * s; e[jj + 1] = av.y > 0 ? s : NEG_INF_F;
                s = my_src + dv.z; s = s > 0.f ? s : 0.01f * s; e[jj + 2] = av.z > 0 ? s : NEG_INF_F;
                s = my_src + dv.w; s = s > 0.f ? s : 0.01f * s; e[jj + 3] = av.w > 0 ? s : NEG_INF_F;
            }
        }
        float tm = NEG_INF_F;
#pragma unroll
        for (int jj = 0; jj < 16; jj++) tm = fmaxf(tm, e[jj]);
        tm = fmaxf(tm, __shfl_xor_sync(~0u, tm, 1));
        tm = fmaxf(tm, __shfl_xor_sync(~0u, tm, 2));

        float m_new = fmaxf(m, tm);
        float sc = __expf(m - m_new);
        l *= sc;

        float sp = 0.f;
#pragma unroll
        for (int jj = 0; jj < 16; jj++) {
            float p = __expf(e[jj] - m_new);
            sp += p;
            ull pd; PACK2(pd, p);
            p2_s[(q * 16 + jj) * 64 + ti] = pd;
        }
        sp += __shfl_xor_sync(~0u, sp, 1);
        sp += __shfl_xor_sync(~0u, sp, 2);
        l += sp;
        m = m_new;
        if (q == 0) scale_s[ti] = sc;

        __syncthreads();   // p2_s / wh_s / scale_s ready

        // ---- PV phase: 4x8 microtile GEMM ----
        {
            float4 scv = *(const float4*)(scale_s + i0);
            ull s0, s1, s2, s3;
            PACK2(s0, scv.x); PACK2(s1, scv.y); PACK2(s2, scv.z); PACK2(s3, scv.w);
#pragma unroll
            for (int c = 0; c < 4; c++) {
                MUL2(acc2[0 * 4 + c], s0);
                MUL2(acc2[1 * 4 + c], s1);
                MUL2(acc2[2 * 4 + c], s2);
                MUL2(acc2[3 * 4 + c], s3);
            }

#pragma unroll 8
            for (int k = 0; k < 64; k++) {
                const ulonglong2* pp = (const ulonglong2*)(p2_s + k * 64 + i0);
                ulonglong2 pA = pp[0];   // rows i0, i0+1
                ulonglong2 pB = pp[1];   // rows i0+2, i0+3
                const ulonglong2* ww = (const ulonglong2*)(wh_s + k * 128 + h0);
                ulonglong2 wA = ww[0];   // h0..h0+3
                ulonglong2 wB = ww[1];   // h0+4..h0+7
                FMA2(acc2[0],  wA.x, pA.x); FMA2(acc2[1],  wA.y, pA.x);
                FMA2(acc2[2],  wB.x, pA.x); FMA2(acc2[3],  wB.y, pA.x);
                FMA2(acc2[4],  wA.x, pA.y); FMA2(acc2[5],  wA.y, pA.y);
                FMA2(acc2[6],  wB.x, pA.y); FMA2(acc2[7],  wB.y, pA.y);
                FMA2(acc2[8],  wA.x, pB.x); FMA2(acc2[9],  wA.y, pB.x);
                FMA2(acc2[10], wB.x, pB.x); FMA2(acc2[11], wB.y, pB.x);
                FMA2(acc2[12], wA.x, pB.y); FMA2(acc2[13], wA.y, pB.y);
                FMA2(acc2[14], wB.x, pB.y); FMA2(acc2[15], wB.y, pB.y);
            }
        }
    }

    if (q == 0) l_s[ti] = l;
    __syncthreads();

    // ---- epilogue: normalize, ELU, store ----
    float4 lv = *(const float4*)(l_s + i0);
    float invl[4] = {1.f / lv.x, 1.f / lv.y, 1.f / lv.z, 1.f / lv.w};
#pragma unroll
    for (int r = 0; r < 4; r++) {
        float* orow = out + ((size_t)b * N_ + blockIdx.x * 64 + i0 + r) * H_ + h0;
        float v[8];
#pragma unroll
        for (int c = 0; c < 4; c++)
            asm("mov.b64 {%0, %1}, %2;" : "=f"(v[2 * c]), "=f"(v[2 * c + 1]) : "l"(acc2[r * 4 + c]));
        float4 o0, o1;
        float x;
        x = v[0] * invl[r]; o0.x = x > 0.f ? x : expm1f(x);
        x = v[1] * invl[r]; o0.y = x > 0.f ? x : expm1f(x);
        x = v[2] * invl[r]; o0.z = x > 0.f ? x : expm1f(x);
        x = v[3] * invl[r]; o0.w = x > 0.f ? x : expm1f(x);
        x = v[4] * invl[r]; o1.x = x > 0.f ? x : expm1f(x);
        x = v[5] * invl[r]; o1.y = x > 0.f ? x : expm1f(x);
        x = v[6] * invl[r]; o1.z = x > 0.f ? x : expm1f(x);
        x = v[7] * invl[r]; o1.w = x > 0.f ? x : expm1f(x);
        *(float4*)(orow + 0) = o0;
        *(float4*)(orow + 4) = o1;
    }
}

// ---------------------------------------------------------------------------
extern "C" void kernel_launch(void* const* d_in, const int* in_sizes, int n_in,
                              void* d_out, int out_size) {
    const float* inputs = (const float*)d_in[0];
    const int*   adj    = (const int*)d_in[1];
    const float* W      = (const float*)d_in[2];
    const float* bW     = (const float*)d_in[3];
    const float* a      = (const float*)d_in[4];
    const float* b_a    = (const float*)d_in[5];
    float* out = (float*)d_out;

    cudaFuncSetAttribute(k_attn, cudaFuncAttributeMaxDynamicSharedMemorySize, SMEM_TOTAL);

    k_proj<<<(B_ * N_) / 128, 256>>>(inputs, W, bW);
    k_srcdst<<<(B_ * N_) / 8, 256>>>(a, b_a);
    k_attn<<<dim3(N_ / 64, B_), 256, SMEM_TOTAL>>>(adj, out);
}

// round 3
// speedup vs baseline: 2.1641x; 1.5261x over previous
#include <cuda_runtime.h>
#include <cstdint>
#include <math.h>

#define B_   16
#define N_   2048
#define FIN  256
#define H_   128
#define NEG_INF_F (-9000000000000000.0f)

typedef unsigned long long ull;

// Scratch (allocation-free: __device__ globals)
__device__ float g_wh[B_ * N_ * H_];     // 16.8 MB
__device__ float g_src[B_ * N_];         // src + b_a folded in
__device__ float g_dst[B_ * N_];

// ---------------------------------------------------------------------------
// Kernel A: wh[r][h] = sum_f inputs[r][f] * W[h][f] + b_W[h]
// ---------------------------------------------------------------------------
__global__ __launch_bounds__(256) void k_proj(const float* __restrict__ inp,
                                              const float* __restrict__ W,
                                              const float* __restrict__ bW) {
    __shared__ __align__(16) float A_s[32 * 132];
    __shared__ __align__(16) float W_s[32 * 132];
    int t = threadIdx.x;
    int row0 = blockIdx.x * 128;
    int tr = t >> 4, tc = t & 15;

    float acc[8][8];
#pragma unroll
    for (int i = 0; i < 8; i++)
#pragma unroll
        for (int j = 0; j < 8; j++) acc[i][j] = 0.f;

    for (int k0 = 0; k0 < FIN; k0 += 32) {
#pragma unroll
        for (int v = 0; v < 4; v++) {
            int f4 = t + 256 * v;
            int r = f4 >> 3;
            int c = (f4 & 7) * 4;
            float4 a = *(const float4*)(inp + (size_t)(row0 + r) * FIN + k0 + c);
            A_s[(c + 0) * 132 + r] = a.x;
            A_s[(c + 1) * 132 + r] = a.y;
            A_s[(c + 2) * 132 + r] = a.z;
            A_s[(c + 3) * 132 + r] = a.w;
            float4 b = *(const float4*)(W + (size_t)r * FIN + k0 + c);
            W_s[(c + 0) * 132 + r] = b.x;
            W_s[(c + 1) * 132 + r] = b.y;
            W_s[(c + 2) * 132 + r] = b.z;
            W_s[(c + 3) * 132 + r] = b.w;
        }
        __syncthreads();
#pragma unroll
        for (int kk = 0; kk < 32; kk++) {
            float a[8], b[8];
            *(float4*)&a[0] = *(const float4*)&A_s[kk * 132 + tr * 8];
            *(float4*)&a[4] = *(const float4*)&A_s[kk * 132 + tr * 8 + 4];
            *(float4*)&b[0] = *(const float4*)&W_s[kk * 132 + tc * 8];
            *(float4*)&b[4] = *(const float4*)&W_s[kk * 132 + tc * 8 + 4];
#pragma unroll
            for (int i = 0; i < 8; i++)
#pragma unroll
                for (int j = 0; j < 8; j++)
                    acc[i][j] = fmaf(a[i], b[j], acc[i][j]);
        }
        __syncthreads();
    }

#pragma unroll
    for (int i = 0; i < 8; i++) {
        int r = row0 + tr * 8 + i;
#pragma unroll
        for (int j = 0; j < 8; j += 4) {
            int h = tc * 8 + j;
            float4 o;
            o.x = acc[i][j + 0] + bW[h + 0];
            o.y = acc[i][j + 1] + bW[h + 1];
            o.z = acc[i][j + 2] + bW[h + 2];
            o.w = acc[i][j + 3] + bW[h + 3];
            *(float4*)(g_wh + (size_t)r * H_ + h) = o;
        }
    }
}

// ---------------------------------------------------------------------------
// Kernel B: src[r] = wh[r]·a1 + b_a ; dst[r] = wh[r]·a2.
// ---------------------------------------------------------------------------
__global__ __launch_bounds__(256) void k_srcdst(const float* __restrict__ a,
                                                const float* __restrict__ b_a) {
    int row = blockIdx.x * 8 + (threadIdx.x >> 5);
    int lane = threadIdx.x & 31;
    float4 wv = *(const float4*)(g_wh + (size_t)row * H_ + lane * 4);
    float4 a1 = *(const float4*)(a + lane * 4);
    float4 a2 = *(const float4*)(a + H_ + lane * 4);
    float s1 = wv.x * a1.x + wv.y * a1.y + wv.z * a1.z + wv.w * a1.w;
    float s2 = wv.x * a2.x + wv.y * a2.y + wv.z * a2.z + wv.w * a2.w;
#pragma unroll
    for (int o = 16; o; o >>= 1) {
        s1 += __shfl_xor_sync(~0u, s1, o);
        s2 += __shfl_xor_sync(~0u, s2, o);
    }
    if (lane == 0) {
        g_src[row] = s1 + b_a[0];
        g_dst[row] = s2;
    }
}

// ---------------------------------------------------------------------------
// Kernel C: fused masked-softmax attention + ELU.
//
// Block = 128 i-rows of one batch, 256 threads, j-tiles of 32.
//
// Score phase: thread (ti=t>>1, q=t&1) computes 16 scores for row ti,
//   online-softmax m/l in registers (pair combined via shfl_xor 1),
//   writes p duplicated {p,p} into p2_s[32 k][128 i].
//
// PV phase: thread (tv=t>>4, th=t&15) owns an 8(i) x 8(h) microtile.
//   wh_s rows are chunk-permuted: 16B chunk ci stored at slot
//   perm(ci) = (ci&1)*16 + (ci>>1), so wA (slot th) and wB (slot 16+th)
//   are read by contiguous lanes -> conflict-free.
//   Per k: 4 LDS.128 (p-pairs, broadcast) + 2 LDS.128 (w) + 32 fma.rn.f32x2.
// ---------------------------------------------------------------------------
#define TJ 32
#define SMEM_WH    0
#define SMEM_P2    (TJ * 128 * 4)                  // 16384
#define SMEM_SCALE (SMEM_P2 + TJ * 128 * 8)        // 49152
#define SMEM_L     (SMEM_SCALE + 512)              // 49664
#define SMEM_TOTAL (SMEM_L + 512)                  // 50176

#define FMA2(acc, w, p) asm("fma.rn.f32x2 %0, %1, %2, %0;" : "+l"(acc) : "l"(w), "l"(p))
#define MUL2(acc, s)    asm("mul.rn.f32x2 %0, %0, %1;" : "+l"(acc) : "l"(s))
#define PACK2(d, f)     asm("mov.b64 %0, {%1, %1};" : "=l"(d) : "f"(f))

__global__ __launch_bounds__(256, 2) void k_attn(const int* __restrict__ adj,
                                                 float* __restrict__ out) {
    extern __shared__ __align__(16) char smem_raw[];
    float* wh_s    = (float*)(smem_raw + SMEM_WH);    // [32 k][128] permuted
    ull*   p2_s    = (ull*)  (smem_raw + SMEM_P2);    // [32 k][128 i] {p,p}
    float* scale_s = (float*)(smem_raw + SMEM_SCALE); // [128]
    float* l_s     = (float*)(smem_raw + SMEM_L);     // [128]

    int t = threadIdx.x;
    // score mapping: 2 threads per row
    int ti = t >> 1, q = t & 1;
    // PV mapping: 8x8 microtile
    int tv = t >> 4, th = t & 15;
    int i0 = tv * 8, h0 = th * 8;

    int b = blockIdx.y;
    int ibase = blockIdx.x * 128;

    float my_src = g_src[b * N_ + ibase + ti];
    float m = NEG_INF_F, l = 0.f;

    ull acc2[32];   // [r 0..7][c 0..3]; c -> h = h0 + 2c, 2c+1
#pragma unroll
    for (int u = 0; u < 32; u++) acc2[u] = 0ull;

    const int*   adj_row = adj + ((size_t)(b * N_ + ibase + ti)) * (size_t)N_;
    const float* dst_row = g_dst + b * N_;

    for (int j0 = 0; j0 < N_; j0 += TJ) {
        __syncthreads();   // previous tile's PV reads done

        // ---- stage wh tile [32][128], chunk-permuted ----
#pragma unroll
        for (int v = 0; v < 4; v++) {
            int idx = t + 256 * v;          // float4 index
            int k  = idx >> 5;              // 0..31
            int ci = idx & 31;              // 16B chunk within row
            float4 val = *(const float4*)(g_wh + ((size_t)(b * N_ + j0 + k)) * H_ + ci * 4);
            int pc = ((ci & 1) << 4) | (ci >> 1);
            *(float4*)(wh_s + k * 128 + pc * 4) = val;
        }

        // ---- score phase: 16 j's = [j0 + q*16, +16) for row ti ----
        float e[16];
        {
            const int4*   a4 = (const int4*)(adj_row + j0 + q * 16);
            const float4* d4 = (const float4*)(dst_row + j0 + q * 16);
#pragma unroll
            for (int v = 0; v < 4; v++) {
                int4 av = a4[v];
                float4 dv = d4[v];
                int jj = v * 4;
                float s;
                s = my_src + dv.x; s = s > 0.f ? s : 0.01f * s; e[jj + 0] = av.x > 0 ? s : NEG_INF_F;
                s = my_src + dv.y; s = s > 0.f ? s : 0.01f * s; e[jj + 1] = av.y > 0 ? s : NEG_INF_F;
                s = my_src + dv.z; s = s > 0.f ? s : 0.01f * s; e[jj + 2] = av.z > 0 ? s : NEG_INF_F;
                s = my_src + dv.w; s = s > 0.f ? s : 0.01f * s; e[jj + 3] = av.w > 0 ? s : NEG_INF_F;
            }
        }
        float tm = NEG_INF_F;
#pragma unroll
        for (int jj = 0; jj < 16; jj++) tm = fmaxf(tm, e[jj]);
        tm = fmaxf(tm, __shfl_xor_sync(~0u, tm, 1));

        float m_new = fmaxf(m, tm);
        float sc = __expf(m - m_new);
        l *= sc;

        float sp = 0.f;
#pragma unroll
        for (int jj = 0; jj < 16; jj++) {
            float p = __expf(e[jj] - m_new);
            sp += p;
            ull pd; PACK2(pd, p);
            p2_s[(q * 16 + jj) * 128 + ti] = pd;
        }
        sp += __shfl_xor_sync(~0u, sp, 1);
        l += sp;
        m = m_new;
        if (q == 0) scale_s[ti] = sc;

        __syncthreads();   // p2_s / wh_s / scale_s ready

        // ---- PV phase: 8x8 microtile ----
        {
            float4 sc0 = *(const float4*)(scale_s + i0);
            float4 sc1 = *(const float4*)(scale_s + i0 + 4);
            ull sd[8];
            PACK2(sd[0], sc0.x); PACK2(sd[1], sc0.y); PACK2(sd[2], sc0.z); PACK2(sd[3], sc0.w);
            PACK2(sd[4], sc1.x); PACK2(sd[5], sc1.y); PACK2(sd[6], sc1.z); PACK2(sd[7], sc1.w);
#pragma unroll
            for (int r = 0; r < 8; r++)
#pragma unroll
                for (int c = 0; c < 4; c++)
                    MUL2(acc2[r * 4 + c], sd[r]);

#pragma unroll 8
            for (int k = 0; k < TJ; k++) {
                const ulonglong2* pp = (const ulonglong2*)(p2_s + k * 128 + i0);
                ulonglong2 p01 = pp[0];  // rows i0,   i0+1
                ulonglong2 p23 = pp[1];  // rows i0+2, i0+3
                ulonglong2 p45 = pp[2];
                ulonglong2 p67 = pp[3];
                ulonglong2 wA = *(const ulonglong2*)(wh_s + k * 128 + th * 4);       // h0..h0+3
                ulonglong2 wB = *(const ulonglong2*)(wh_s + k * 128 + 64 + th * 4);  // h0+4..h0+7
                FMA2(acc2[0],  wA.x, p01.x); FMA2(acc2[1],  wA.y, p01.x);
                FMA2(acc2[2],  wB.x, p01.x); FMA2(acc2[3],  wB.y, p01.x);
                FMA2(acc2[4],  wA.x, p01.y); FMA2(acc2[5],  wA.y, p01.y);
                FMA2(acc2[6],  wB.x, p01.y); FMA2(acc2[7],  wB.y, p01.y);
                FMA2(acc2[8],  wA.x, p23.x); FMA2(acc2[9],  wA.y, p23.x);
                FMA2(acc2[10], wB.x, p23.x); FMA2(acc2[11], wB.y, p23.x);
                FMA2(acc2[12], wA.x, p23.y); FMA2(acc2[13], wA.y, p23.y);
                FMA2(acc2[14], wB.x, p23.y); FMA2(acc2[15], wB.y, p23.y);
                FMA2(acc2[16], wA.x, p45.x); FMA2(acc2[17], wA.y, p45.x);
                FMA2(acc2[18], wB.x, p45.x); FMA2(acc2[19], wB.y, p45.x);
                FMA2(acc2[20], wA.x, p45.y); FMA2(acc2[21], wA.y, p45.y);
                FMA2(acc2[22], wB.x, p45.y); FMA2(acc2[23], wB.y, p45.y);
                FMA2(acc2[24], wA.x, p67.x); FMA2(acc2[25], wA.y, p67.x);
                FMA2(acc2[26], wB.x, p67.x); FMA2(acc2[27], wB.y, p67.x);
                FMA2(acc2[28], wA.x, p67.y); FMA2(acc2[29], wA.y, p67.y);
                FMA2(acc2[30], wB.x, p67.y); FMA2(acc2[31], wB.y, p67.y);
            }
        }
    }

    if (q == 0) l_s[ti] = l;
    __syncthreads();

    // ---- epilogue: normalize, ELU, store ----
    float4 lv0 = *(const float4*)(l_s + i0);
    float4 lv1 = *(const float4*)(l_s + i0 + 4);
    float invl[8] = {1.f / lv0.x, 1.f / lv0.y, 1.f / lv0.z, 1.f / lv0.w,
                     1.f / lv1.x, 1.f / lv1.y, 1.f / lv1.z, 1.f / lv1.w};
#pragma unroll
    for (int r = 0; r < 8; r++) {
        float* orow = out + ((size_t)(b * N_ + ibase + i0 + r)) * H_ + h0;
        float v[8];
#pragma unroll
        for (int c = 0; c < 4; c++)
            asm("mov.b64 {%0, %1}, %2;" : "=f"(v[2 * c]), "=f"(v[2 * c + 1]) : "l"(acc2[r * 4 + c]));
        float4 o0, o1;
        float x;
        x = v[0] * invl[r]; o0.x = x > 0.f ? x : expm1f(x);
        x = v[1] * invl[r]; o0.y = x > 0.f ? x : expm1f(x);
        x = v[2] * invl[r]; o0.z = x > 0.f ? x : expm1f(x);
        x = v[3] * invl[r]; o0.w = x > 0.f ? x : expm1f(x);
        x = v[4] * invl[r]; o1.x = x > 0.f ? x : expm1f(x);
        x = v[5] * invl[r]; o1.y = x > 0.f ? x : expm1f(x);
        x = v[6] * invl[r]; o1.z = x > 0.f ? x : expm1f(x);
        x = v[7] * invl[r]; o1.w = x > 0.f ? x : expm1f(x);
        *(float4*)(orow + 0) = o0;
        *(float4*)(orow + 4) = o1;
    }
}

// ---------------------------------------------------------------------------
extern "C" void kernel_launch(void* const* d_in, const int* in_sizes, int n_in,
                              void* d_out, int out_size) {
    const float* inputs = (const float*)d_in[0];
    const int*   adj    = (const int*)d_in[1];
    const float* W      = (const float*)d_in[2];
    const float* bW     = (const float*)d_in[3];
    const float* a      = (const float*)d_in[4];
    const float* b_a    = (const float*)d_in[5];
    float* out = (float*)d_out;

    cudaFuncSetAttribute(k_attn, cudaFuncAttributeMaxDynamicSharedMemorySize, SMEM_TOTAL);

    k_proj<<<(B_ * N_) / 128, 256>>>(inputs, W, bW);
    k_srcdst<<<(B_ * N_) / 8, 256>>>(a, b_a);
    k_attn<<<dim3(N_ / 128, B_), 256, SMEM_TOTAL>>>(adj, out);
}

// round 5
// speedup vs baseline: 3.9046x; 1.8042x over previous
#include <cuda_runtime.h>
#include <cuda_fp16.h>
#include <cstdint>
#include <math.h>

#define B_   16
#define N_   2048
#define FIN  256
#define H_   128
#define TJ   32
#define NEG_INF_F (-9000000000000000.0f)

// Scratch (allocation-free: __device__ globals)
__device__ float g_wh[B_ * N_ * H_];         // [b][n][h] fp32
__device__ half  g_whT_hi[B_ * H_ * N_];     // [b][h][n] fp16 hi
__device__ half  g_whT_lo[B_ * H_ * N_];     // [b][h][n] fp16 lo
__device__ float g_src[B_ * N_];             // src + b_a folded in
__device__ float g_dst[B_ * N_];
__device__ float g_dstmax[B_];

__device__ __forceinline__ uint32_t smem_u32(const void* p) {
    uint32_t a;
    asm("{ .reg .u64 t; cvta.to.shared.u64 t, %1; cvt.u32.u64 %0, t; }" : "=r"(a) : "l"(p));
    return a;
}

#define LDSM4(r0, r1, r2, r3, addr) \
    asm volatile("ldmatrix.sync.aligned.m8n8.x4.shared.b16 {%0,%1,%2,%3}, [%4];" \
                 : "=r"(r0), "=r"(r1), "=r"(r2), "=r"(r3) : "r"(addr))

#define MMA16816(d, a0, a1, a2, a3, b0, b1) \
    asm volatile("mma.sync.aligned.m16n8k16.row.col.f32.f16.f16.f32 " \
                 "{%0,%1,%2,%3}, {%4,%5,%6,%7}, {%8,%9}, {%0,%1,%2,%3};" \
                 : "+f"((d)[0]), "+f"((d)[1]), "+f"((d)[2]), "+f"((d)[3]) \
                 : "r"(a0), "r"(a1), "r"(a2), "r"(a3), "r"(b0), "r"(b1))

// ---------------------------------------------------------------------------
// Kernel A: wh[r][h] = sum_f inputs[r][f] * W[h][f] + b_W[h]
// ---------------------------------------------------------------------------
__global__ __launch_bounds__(256) void k_proj(const float* __restrict__ inp,
                                              const float* __restrict__ W,
                                              const float* __restrict__ bW) {
    __shared__ __align__(16) float A_s[32 * 132];
    __shared__ __align__(16) float W_s[32 * 132];
    int t = threadIdx.x;
    int row0 = blockIdx.x * 128;
    int tr = t >> 4, tc = t & 15;

    float acc[8][8];
#pragma unroll
    for (int i = 0; i < 8; i++)
#pragma unroll
        for (int j = 0; j < 8; j++) acc[i][j] = 0.f;

    for (int k0 = 0; k0 < FIN; k0 += 32) {
#pragma unroll
        for (int v = 0; v < 4; v++) {
            int f4 = t + 256 * v;
            int r = f4 >> 3;
            int c = (f4 & 7) * 4;
            float4 a = *(const float4*)(inp + (size_t)(row0 + r) * FIN + k0 + c);
            A_s[(c + 0) * 132 + r] = a.x;
            A_s[(c + 1) * 132 + r] = a.y;
            A_s[(c + 2) * 132 + r] = a.z;
            A_s[(c + 3) * 132 + r] = a.w;
            float4 b = *(const float4*)(W + (size_t)r * FIN + k0 + c);
            W_s[(c + 0) * 132 + r] = b.x;
            W_s[(c + 1) * 132 + r] = b.y;
            W_s[(c + 2) * 132 + r] = b.z;
            W_s[(c + 3) * 132 + r] = b.w;
        }
        __syncthreads();
#pragma unroll
        for (int kk = 0; kk < 32; kk++) {
            float a[8], b[8];
            *(float4*)&a[0] = *(const float4*)&A_s[kk * 132 + tr * 8];
            *(float4*)&a[4] = *(const float4*)&A_s[kk * 132 + tr * 8 + 4];
            *(float4*)&b[0] = *(const float4*)&W_s[kk * 132 + tc * 8];
            *(float4*)&b[4] = *(const float4*)&W_s[kk * 132 + tc * 8 + 4];
#pragma unroll
            for (int i = 0; i < 8; i++)
#pragma unroll
                for (int j = 0; j < 8; j++)
                    acc[i][j] = fmaf(a[i], b[j], acc[i][j]);
        }
        __syncthreads();
    }

#pragma unroll
    for (int i = 0; i < 8; i++) {
        int r = row0 + tr * 8 + i;
#pragma unroll
        for (int j = 0; j < 8; j += 4) {
            int h = tc * 8 + j;
            float4 o;
            o.x = acc[i][j + 0] + bW[h + 0];
            o.y = acc[i][j + 1] + bW[h + 1];
            o.z = acc[i][j + 2] + bW[h + 2];
            o.w = acc[i][j + 3] + bW[h + 3];
            *(float4*)(g_wh + (size_t)r * H_ + h) = o;
        }
    }
}

// ---------------------------------------------------------------------------
// Kernel B: src[r] = wh[r]·a1 + b_a ; dst[r] = wh[r]·a2.
// ---------------------------------------------------------------------------
__global__ __launch_bounds__(256) void k_srcdst(const float* __restrict__ a,
                                                const float* __restrict__ b_a) {
    int row = blockIdx.x * 8 + (threadIdx.x >> 5);
    int lane = threadIdx.x & 31;
    float4 wv = *(const float4*)(g_wh + (size_t)row * H_ + lane * 4);
    float4 a1 = *(const float4*)(a + lane * 4);
    float4 a2 = *(const float4*)(a + H_ + lane * 4);
    float s1 = wv.x * a1.x + wv.y * a1.y + wv.z * a1.z + wv.w * a1.w;
    float s2 = wv.x * a2.x + wv.y * a2.y + wv.z * a2.z + wv.w * a2.w;
#pragma unroll
    for (int o = 16; o; o >>= 1) {
        s1 += __shfl_xor_sync(~0u, s1, o);
        s2 += __shfl_xor_sync(~0u, s2, o);
    }
    if (lane == 0) {
        g_src[row] = s1 + b_a[0];
        g_dst[row] = s2;
    }
}

// ---------------------------------------------------------------------------
// Kernel B2: per-batch max of dst (softmax upper bound).
// ---------------------------------------------------------------------------
__global__ __launch_bounds__(256) void k_dstmax() {
    __shared__ float red[8];
    int b = blockIdx.x, t = threadIdx.x;
    float mx = -1e30f;
#pragma unroll
    for (int v = 0; v < 8; v++) mx = fmaxf(mx, g_dst[b * N_ + t + 256 * v]);
#pragma unroll
    for (int o = 16; o; o >>= 1) mx = fmaxf(mx, __shfl_xor_sync(~0u, mx, o));
    if ((t & 31) == 0) red[t >> 5] = mx;
    __syncthreads();
    if (t == 0) {
        float m2 = red[0];
#pragma unroll
        for (int i = 1; i < 8; i++) m2 = fmaxf(m2, red[i]);
        g_dstmax[b] = m2;
    }
}

// ---------------------------------------------------------------------------
// Kernel B3: transpose + fp16 split: wh[b][n][h] -> whT_hi/lo[b][h][n]
// ---------------------------------------------------------------------------
__global__ __launch_bounds__(256) void k_whT() {
    __shared__ float tile[32][33];
    int b = blockIdx.z;
    int j0 = blockIdx.x * 32, h0 = blockIdx.y * 32;
    int tx = threadIdx.x & 31, ty = threadIdx.x >> 5;
#pragma unroll
    for (int k = 0; k < 4; k++) {
        int j = j0 + ty + k * 8;
        tile[ty + k * 8][tx] = g_wh[((size_t)(b * N_ + j)) * H_ + h0 + tx];
    }
    __syncthreads();
#pragma unroll
    for (int k = 0; k < 4; k++) {
        int h = h0 + ty + k * 8;
        float v = tile[tx][ty + k * 8];
        half hi = __float2half_rn(v);
        half lo = __float2half_rn(v - __half2float(hi));
        size_t idx = ((size_t)(b * H_ + h)) * N_ + j0 + tx;
        g_whT_hi[idx] = hi;
        g_whT_lo[idx] = lo;
    }
}

// ---------------------------------------------------------------------------
// Kernel C: fused attention via mma.sync (fp16 2-way split, 3 MMAs).
//
// CTA = 128 i x 128 h x 1 batch, 256 threads (8 warps), j-tiles of 32.
// Fixed softmax bound m_i = LR(src_i + dstmax_b), single-pass P.
// Warp w owns i rows [16w,16w+16); accumulators C[16 ntiles][4] fp32 regs.
// smem: P_hi/P_lo [128][40] halfs, whT_hi/lo [128][40] halfs (80B rows,
// conflict-free ldmatrix).
// ---------------------------------------------------------------------------
__global__ __launch_bounds__(256, 2) void k_attn_mma(const int* __restrict__ adj,
                                                     float* __restrict__ out) {
    __shared__ __align__(16) half Ph_s[128 * 40];
    __shared__ __align__(16) half Pl_s[128 * 40];
    __shared__ __align__(16) half Wh_s[128 * 40];
    __shared__ __align__(16) half Wl_s[128 * 40];
    __shared__ float l_s[128];

    int t = threadIdx.x;
    int w = t >> 5, lane = t & 31;
    int ti = t >> 1, q = t & 1;
    int b = blockIdx.y;
    int ibase = blockIdx.x * 128;

    float my_src = g_src[b * N_ + ibase + ti];
    float mb = my_src + g_dstmax[b];
    float m = mb > 0.f ? mb : 0.01f * mb;
    float l = 0.f;

    const int*   adj_row = adj + ((size_t)(b * N_ + ibase + ti)) * (size_t)N_;
    const float* dst_row = g_dst + b * N_;
    const half*  whTh_b  = g_whT_hi + (size_t)b * H_ * N_;
    const half*  whTl_b  = g_whT_lo + (size_t)b * H_ * N_;

    float C[16][4];
#pragma unroll
    for (int nt = 0; nt < 16; nt++)
#pragma unroll
        for (int c = 0; c < 4; c++) C[nt][c] = 0.f;

    // ldmatrix source addresses (computed once)
    uint32_t a_addr_base = smem_u32(Ph_s + (16 * w + (lane & 15)) * 40 + (lane >> 4) * 8);
    uint32_t al_addr_base = a_addr_base + (uint32_t)((char*)Pl_s - (char*)Ph_s);
    int bn = ((lane >> 4) & 1) * 8 + (lane & 7);   // row within 16-n group
    int bk = ((lane >> 3) & 1) * 8;                // k offset
    uint32_t b_addr_base = smem_u32(Wh_s + bn * 40 + bk);
    uint32_t bl_addr_base = b_addr_base + (uint32_t)((char*)Wl_s - (char*)Wh_s);

    for (int tile = 0; tile < 64; tile++) {
        int j0 = tile * TJ;
        __syncthreads();   // previous tile's mma reads done

        // ---- stage whT hi/lo tile: [128 h][32 j] ----
        {
            int hr = t >> 1, hf = t & 1;
            const uint4* gh = (const uint4*)(whTh_b + (size_t)hr * N_ + j0) + hf * 2;
            const uint4* gl = (const uint4*)(whTl_b + (size_t)hr * N_ + j0) + hf * 2;
            uint4* dh = (uint4*)(Wh_s + hr * 40 + hf * 16);
            uint4* dl = (uint4*)(Wl_s + hr * 40 + hf * 16);
            dh[0] = gh[0]; dh[1] = gh[1];
            dl[0] = gl[0]; dl[1] = gl[1];
        }

        // ---- score phase: 16 j's for row ti, split to fp16 hi/lo ----
        {
            const int4*   a4 = (const int4*)(adj_row + j0 + q * 16);
            const float4* d4 = (const float4*)(dst_row + j0 + q * 16);
            __align__(16) half hs[16];
            __align__(16) half ls[16];
#pragma unroll
            for (int v2 = 0; v2 < 4; v2++) {
                int4 av = a4[v2];
                float4 dv = d4[v2];
                float sc, p, r;
                half hh;
                int jj = v2 * 4;
                sc = my_src + dv.x; sc = sc > 0.f ? sc : 0.01f * sc;
                p = av.x > 0 ? __expf(sc - m) : 0.f; l += p;
                hh = __float2half_rn(p); r = p - __half2float(hh);
                hs[jj + 0] = hh; ls[jj + 0] = __float2half_rn(r);
                sc = my_src + dv.y; sc = sc > 0.f ? sc : 0.01f * sc;
                p = av.y > 0 ? __expf(sc - m) : 0.f; l += p;
                hh = __float2half_rn(p); r = p - __half2float(hh);
                hs[jj + 1] = hh; ls[jj + 1] = __float2half_rn(r);
                sc = my_src + dv.z; sc = sc > 0.f ? sc : 0.01f * sc;
                p = av.z > 0 ? __expf(sc - m) : 0.f; l += p;
                hh = __float2half_rn(p); r = p - __half2float(hh);
                hs[jj + 2] = hh; ls[jj + 2] = __float2half_rn(r);
                sc = my_src + dv.w; sc = sc > 0.f ? sc : 0.01f * sc;
                p = av.w > 0 ? __expf(sc - m) : 0.f; l += p;
                hh = __float2half_rn(p); r = p - __half2float(hh);
                hs[jj + 3] = hh; ls[jj + 3] = __float2half_rn(r);
            }
            uint4* ph = (uint4*)(Ph_s + ti * 40 + q * 16);
            uint4* pl = (uint4*)(Pl_s + ti * 40 + q * 16);
            ph[0] = ((uint4*)hs)[0]; ph[1] = ((uint4*)hs)[1];
            pl[0] = ((uint4*)ls)[0]; pl[1] = ((uint4*)ls)[1];
        }

        __syncthreads();   // tiles ready

        // ---- MMA phase: 2 k16 chunks ----
#pragma unroll
        for (int kc = 0; kc < 2; kc++) {
            uint32_t Ah0, Ah1, Ah2, Ah3, Al0, Al1, Al2, Al3;
            LDSM4(Ah0, Ah1, Ah2, Ah3, a_addr_base + kc * 32);
            LDSM4(Al0, Al1, Al2, Al3, al_addr_base + kc * 32);
#pragma unroll
            for (int np = 0; np < 8; np++) {
                uint32_t Bh0, Bh1, Bh2, Bh3, Bl0, Bl1, Bl2, Bl3;
                LDSM4(Bh0, Bh1, Bh2, Bh3, b_addr_base + np * (16 * 80) + kc * 32);
                LDSM4(Bl0, Bl1, Bl2, Bl3, bl_addr_base + np * (16 * 80) + kc * 32);
                MMA16816(C[np * 2 + 0], Ah0, Ah1, Ah2, Ah3, Bh0, Bh1);
                MMA16816(C[np * 2 + 0], Ah0, Ah1, Ah2, Ah3, Bl0, Bl1);
                MMA16816(C[np * 2 + 0], Al0, Al1, Al2, Al3, Bh0, Bh1);
                MMA16816(C[np * 2 + 1], Ah0, Ah1, Ah2, Ah3, Bh2, Bh3);
                MMA16816(C[np * 2 + 1], Ah0, Ah1, Ah2, Ah3, Bl2, Bl3);
                MMA16816(C[np * 2 + 1], Al0, Al1, Al2, Al3, Bh2, Bh3);
            }
        }
    }

    l += __shfl_xor_sync(~0u, l, 1);
    if (q == 0) l_s[ti] = l;
    __syncthreads();

    // ---- epilogue: normalize, ELU, store from fragments ----
    {
        int r0 = 16 * w + (lane >> 2);
        int r1 = r0 + 8;
        float inv0 = 1.0f / l_s[r0];
        float inv1 = 1.0f / l_s[r1];
        float* orow0 = out + ((size_t)(b * N_ + ibase + r0)) * H_;
        float* orow1 = out + ((size_t)(b * N_ + ibase + r1)) * H_;
        int hoff = (lane & 3) * 2;
#pragma unroll
        for (int nt = 0; nt < 16; nt++) {
            int h = nt * 8 + hoff;
            float x;
            float2 o;
            x = C[nt][0] * inv0; o.x = x > 0.f ? x : expm1f(x);
            x = C[nt][1] * inv0; o.y = x > 0.f ? x : expm1f(x);
            *(float2*)(orow0 + h) = o;
            x = C[nt][2] * inv1; o.x = x > 0.f ? x : expm1f(x);
            x = C[nt][3] * inv1; o.y = x > 0.f ? x : expm1f(x);
            *(float2*)(orow1 + h) = o;
        }
    }
}

// ---------------------------------------------------------------------------
extern "C" void kernel_launch(void* const* d_in, const int* in_sizes, int n_in,
                              void* d_out, int out_size) {
    const float* inputs = (const float*)d_in[0];
    const int*   adj    = (const int*)d_in[1];
    const float* W      = (const float*)d_in[2];
    const float* bW     = (const float*)d_in[3];
    const float* a      = (const float*)d_in[4];
    const float* b_a    = (const float*)d_in[5];
    float* out = (float*)d_out;

    k_proj<<<(B_ * N_) / 128, 256>>>(inputs, W, bW);
    k_srcdst<<<(B_ * N_) / 8, 256>>>(a, b_a);
    k_whT<<<dim3(N_ / 32, H_ / 32, B_), 256>>>();
    k_dstmax<<<B_, 256>>>();
    k_attn_mma<<<dim3(N_ / 128, B_), 256>>>(adj, out);
}

// round 6
// speedup vs baseline: 4.4805x; 1.1475x over previous
#include <cuda_runtime.h>
#include <cuda_fp16.h>
#include <cstdint>
#include <math.h>

#define B_   16
#define N_   2048
#define FIN  256
#define H_   128
#define TJ   32
#define NEG_INF_F (-9000000000000000.0f)

// Scratch (allocation-free: __device__ globals)
__device__ half  g_whT_hi[B_ * H_ * N_];     // [b][h][n] fp16 hi
__device__ half  g_whT_lo[B_ * H_ * N_];     // [b][h][n] fp16 lo
__device__ float g_src[B_ * N_];             // src + b_a folded in
__device__ float g_dst[B_ * N_];
__device__ float g_dstmax[B_];

__device__ __forceinline__ uint32_t smem_u32(const void* p) {
    uint32_t a;
    asm("{ .reg .u64 t; cvta.to.shared.u64 t, %1; cvt.u32.u64 %0, t; }" : "=r"(a) : "l"(p));
    return a;
}

#define LDSM4(r0, r1, r2, r3, addr) \
    asm volatile("ldmatrix.sync.aligned.m8n8.x4.shared.b16 {%0,%1,%2,%3}, [%4];" \
                 : "=r"(r0), "=r"(r1), "=r"(r2), "=r"(r3) : "r"(addr))

#define MMA16816(d, a0, a1, a2, a3, b0, b1) \
    asm volatile("mma.sync.aligned.m16n8k16.row.col.f32.f16.f16.f32 " \
                 "{%0,%1,%2,%3}, {%4,%5,%6,%7}, {%8,%9}, {%0,%1,%2,%3};" \
                 : "+f"((d)[0]), "+f"((d)[1]), "+f"((d)[2]), "+f"((d)[3]) \
                 : "r"(a0), "r"(a1), "r"(a2), "r"(a3), "r"(b0), "r"(b1))

#define CP_ASYNC16(dst, src) \
    asm volatile("cp.async.cg.shared.global [%0], [%1], 16;" :: "r"(dst), "l"(src))
#define CP_COMMIT()  asm volatile("cp.async.commit_group;" ::: "memory")
#define CP_WAIT0()   asm volatile("cp.async.wait_group 0;" ::: "memory")

// ---------------------------------------------------------------------------
// Kernel A (fused): wh = inputs@W^T + bW computed in registers, then:
//   - whT_hi/lo [b][h][n] fp16-split transposed stores
//   - src/dst row reductions (xor-shuffle over tc), src has b_a folded in
// No fp32 wh ever touches memory.
// ---------------------------------------------------------------------------
__global__ __launch_bounds__(256) void k_proj(const float* __restrict__ inp,
                                              const float* __restrict__ W,
                                              const float* __restrict__ bW,
                                              const float* __restrict__ av,
                                              const float* __restrict__ b_a) {
    __shared__ __align__(16) float A_s[32 * 132];
    __shared__ __align__(16) float W_s[32 * 132];
    int t = threadIdx.x;
    int row0 = blockIdx.x * 128;
    int tr = t >> 4, tc = t & 15;

    float acc[8][8];
#pragma unroll
    for (int i = 0; i < 8; i++)
#pragma unroll
        for (int j = 0; j < 8; j++) acc[i][j] = 0.f;

    for (int k0 = 0; k0 < FIN; k0 += 32) {
#pragma unroll
        for (int v = 0; v < 4; v++) {
            int f4 = t + 256 * v;
            int r = f4 >> 3;
            int c = (f4 & 7) * 4;
            float4 a4 = *(const float4*)(inp + (size_t)(row0 + r) * FIN + k0 + c);
            A_s[(c + 0) * 132 + r] = a4.x;
            A_s[(c + 1) * 132 + r] = a4.y;
            A_s[(c + 2) * 132 + r] = a4.z;
            A_s[(c + 3) * 132 + r] = a4.w;
            float4 b4 = *(const float4*)(W + (size_t)r * FIN + k0 + c);
            W_s[(c + 0) * 132 + r] = b4.x;
            W_s[(c + 1) * 132 + r] = b4.y;
            W_s[(c + 2) * 132 + r] = b4.z;
            W_s[(c + 3) * 132 + r] = b4.w;
        }
        __syncthreads();
#pragma unroll
        for (int kk = 0; kk < 32; kk++) {
            float a[8], b[8];
            *(float4*)&a[0] = *(const float4*)&A_s[kk * 132 + tr * 8];
            *(float4*)&a[4] = *(const float4*)&A_s[kk * 132 + tr * 8 + 4];
            *(float4*)&b[0] = *(const float4*)&W_s[kk * 132 + tc * 8];
            *(float4*)&b[4] = *(const float4*)&W_s[kk * 132 + tc * 8 + 4];
#pragma unroll
            for (int i = 0; i < 8; i++)
#pragma unroll
                for (int j = 0; j < 8; j++)
                    acc[i][j] = fmaf(a[i], b[j], acc[i][j]);
        }
        __syncthreads();
    }

    // ---- epilogue ----
    int h0 = tc * 8;
    int bb = row0 / N_;
    int n0 = (row0 % N_) + tr * 8;

    float bwv[8];
    *(float4*)&bwv[0] = *(const float4*)(bW + h0);
    *(float4*)&bwv[4] = *(const float4*)(bW + h0 + 4);
#pragma unroll
    for (int i = 0; i < 8; i++)
#pragma unroll
        for (int j = 0; j < 8; j++) acc[i][j] += bwv[j];

    // whT hi/lo transposed stores: for each h (=h0+j), 8 consecutive n values
#pragma unroll
    for (int j = 0; j < 8; j++) {
        __align__(16) half hi8[8];
        __align__(16) half lo8[8];
#pragma unroll
        for (int i = 0; i < 8; i++) {
            half hh = __float2half_rn(acc[i][j]);
            hi8[i] = hh;
            lo8[i] = __float2half_rn(acc[i][j] - __half2float(hh));
        }
        size_t idx = ((size_t)(bb * H_ + h0 + j)) * N_ + n0;
        *(uint4*)(g_whT_hi + idx) = *(uint4*)hi8;
        *(uint4*)(g_whT_lo + idx) = *(uint4*)lo8;
    }

    // src/dst reductions
    float a1v[8], a2v[8];
    *(float4*)&a1v[0] = *(const float4*)(av + h0);
    *(float4*)&a1v[4] = *(const float4*)(av + h0 + 4);
    *(float4*)&a2v[0] = *(const float4*)(av + H_ + h0);
    *(float4*)&a2v[4] = *(const float4*)(av + H_ + h0 + 4);

    float s1[8], s2[8];
#pragma unroll
    for (int i = 0; i < 8; i++) {
        float x1 = 0.f, x2 = 0.f;
#pragma unroll
        for (int j = 0; j < 8; j++) {
            x1 = fmaf(acc[i][j], a1v[j], x1);
            x2 = fmaf(acc[i][j], a2v[j], x2);
        }
        s1[i] = x1; s2[i] = x2;
    }
#pragma unroll
    for (int o = 1; o < 16; o <<= 1) {
#pragma unroll
        for (int i = 0; i < 8; i++) {
            s1[i] += __shfl_xor_sync(~0u, s1[i], o);
            s2[i] += __shfl_xor_sync(~0u, s2[i], o);
        }
    }
    if (tc == 0) {
        float ba = b_a[0];
        int r = row0 + tr * 8;
#pragma unroll
        for (int i = 0; i < 8; i++) {
            g_src[r + i] = s1[i] + ba;
            g_dst[r + i] = s2[i];
        }
    }
}

// ---------------------------------------------------------------------------
// Kernel B2: per-batch max of dst (softmax upper bound).
// ---------------------------------------------------------------------------
__global__ __launch_bounds__(256) void k_dstmax() {
    __shared__ float red[8];
    int b = blockIdx.x, t = threadIdx.x;
    float mx = -1e30f;
#pragma unroll
    for (int v = 0; v < 8; v++) mx = fmaxf(mx, g_dst[b * N_ + t + 256 * v]);
#pragma unroll
    for (int o = 16; o; o >>= 1) mx = fmaxf(mx, __shfl_xor_sync(~0u, mx, o));
    if ((t & 31) == 0) red[t >> 5] = mx;
    __syncthreads();
    if (t == 0) {
        float m2 = red[0];
#pragma unroll
        for (int i = 1; i < 8; i++) m2 = fmaxf(m2, red[i]);
        g_dstmax[b] = m2;
    }
}

// ---------------------------------------------------------------------------
// Kernel C: fused attention via mma.sync (fp16 2-way split, 3 MMAs),
// software-pipelined: cp.async W(t+1) overlaps MMA(t); adj prefetched one
// tile ahead in registers; double-buffered smem; one sync per tile.
//
// Dynamic smem layout (bytes from base):
//   Ph[2]: 0, 10240   Pl[2]: 20480, 30720
//   Wh[2]: 40960, 51200   Wl[2]: 61440, 71680
//   l_s (float[128]): 81920    total 82432
// ---------------------------------------------------------------------------
#define PBUF 10240u
#define OPL  20480u
#define OWH  40960u
#define OWL  61440u
#define OLS  81920u
#define DYNB 82432

__global__ __launch_bounds__(256, 2) void k_attn_mma(const int* __restrict__ adj,
                                                     float* __restrict__ out) {
    extern __shared__ __align__(16) char dyn[];
    uint32_t sb = smem_u32(dyn);

    int t = threadIdx.x;
    int w = t >> 5, lane = t & 31;
    int ti = t >> 1, q = t & 1;
    int b = blockIdx.y;
    int ibase = blockIdx.x * 128;

    float my_src = g_src[b * N_ + ibase + ti];
    float mb = my_src + g_dstmax[b];
    float m = mb > 0.f ? mb : 0.01f * mb;
    float l = 0.f;

    const int*   adj_row = adj + ((size_t)(b * N_ + ibase + ti)) * (size_t)N_;
    const float* dst_row = g_dst + b * N_;
    const half*  whTh_b  = g_whT_hi + (size_t)b * H_ * N_;
    const half*  whTl_b  = g_whT_lo + (size_t)b * H_ * N_;

    float C[16][4];
#pragma unroll
    for (int nt = 0; nt < 16; nt++)
#pragma unroll
        for (int c = 0; c < 4; c++) C[nt][c] = 0.f;

    // ldmatrix base addresses (buffer 0)
    uint32_t a_base  = sb + (16 * w + (lane & 15)) * 80 + (lane >> 4) * 16;        // Ph
    int bn = ((lane >> 4) & 1) * 8 + (lane & 7);
    int bk = ((lane >> 3) & 1) * 8;
    uint32_t b_base  = sb + OWH + bn * 80 + bk * 2;                                 // Wh

    // W staging pattern: hr = t>>1 row, hf = t&1 half (16 j's)
    int hr = t >> 1, hf = t & 1;
    uint32_t wdst_h = sb + OWH + hr * 80 + hf * 32;
    uint32_t wdst_l = sb + OWL + hr * 80 + hf * 32;
    const half* wsrc_h = whTh_b + (size_t)hr * N_ + hf * 16;
    const half* wsrc_l = whTl_b + (size_t)hr * N_ + hf * 16;

    // ---- prologue: stage W(0), prefetch adj(0) ----
    CP_ASYNC16(wdst_h,      wsrc_h);
    CP_ASYNC16(wdst_h + 16, wsrc_h + 8);
    CP_ASYNC16(wdst_l,      wsrc_l);
    CP_ASYNC16(wdst_l + 16, wsrc_l + 8);
    CP_COMMIT();

    int4 adjp[4];
    {
        const int4* a4 = (const int4*)(adj_row + q * 16);
#pragma unroll
        for (int v = 0; v < 4; v++) adjp[v] = a4[v];
    }

    for (int tile = 0; tile < 64; tile++) {
        int s = tile & 1;
        int j0 = tile * TJ;

        // ---- score phase: P(tile) into Ph/Pl[s] ----
        {
            const float4* d4 = (const float4*)(dst_row + j0 + q * 16);
            __align__(16) half hs[16];
            __align__(16) half ls[16];
#pragma unroll
            for (int v2 = 0; v2 < 4; v2++) {
                int4 av = adjp[v2];
                float4 dv = d4[v2];
                float sc, p, r;
                half hh;
                int jj = v2 * 4;
                sc = my_src + dv.x; sc = sc > 0.f ? sc : 0.01f * sc;
                p = av.x > 0 ? __expf(sc - m) : 0.f; l += p;
                hh = __float2half_rn(p); r = p - __half2float(hh);
                hs[jj + 0] = hh; ls[jj + 0] = __float2half_rn(r);
                sc = my_src + dv.y; sc = sc > 0.f ? sc : 0.01f * sc;
                p = av.y > 0 ? __expf(sc - m) : 0.f; l += p;
                hh = __float2half_rn(p); r = p - __half2float(hh);
                hs[jj + 1] = hh; ls[jj + 1] = __float2half_rn(r);
                sc = my_src + dv.z; sc = sc > 0.f ? sc : 0.01f * sc;
                p = av.z > 0 ? __expf(sc - m) : 0.f; l += p;
                hh = __float2half_rn(p); r = p - __half2float(hh);
                hs[jj + 2] = hh; ls[jj + 2] = __float2half_rn(r);
                sc = my_src + dv.w; sc = sc > 0.f ? sc : 0.01f * sc;
                p = av.w > 0 ? __expf(sc - m) : 0.f; l += p;
                hh = __float2half_rn(p); r = p - __half2float(hh);
                hs[jj + 3] = hh; ls[jj + 3] = __float2half_rn(r);
            }
            uint32_t pdst = sb + s * PBUF + ti * 80 + q * 32;
            *(uint4*)(dyn + (pdst - sb))       = ((uint4*)hs)[0];
            *(uint4*)(dyn + (pdst - sb) + 16)  = ((uint4*)hs)[1];
            *(uint4*)(dyn + (pdst - sb) + OPL)      = ((uint4*)ls)[0];
            *(uint4*)(dyn + (pdst - sb) + OPL + 16) = ((uint4*)ls)[1];
        }

        // ---- prefetch adj(tile+1) ----
        {
            int jn = ((tile + 1) & 63) * TJ;
            const int4* a4 = (const int4*)(adj_row + jn + q * 16);
#pragma unroll
            for (int v = 0; v < 4; v++) adjp[v] = a4[v];
        }

        CP_WAIT0();        // W(tile) landed
        __syncthreads();   // P(s) visible; mma(tile-1) done with buffers s^1

        // ---- issue cp.async W(tile+1) into buffer s^1 (overlaps mma) ----
        if (tile < 63) {
            int jn = (tile + 1) * TJ;
            uint32_t off = (s ^ 1) * PBUF;
            CP_ASYNC16(wdst_h + off,      wsrc_h + jn);
            CP_ASYNC16(wdst_h + off + 16, wsrc_h + jn + 8);
            CP_ASYNC16(wdst_l + off,      wsrc_l + jn);
            CP_ASYNC16(wdst_l + off + 16, wsrc_l + jn + 8);
            CP_COMMIT();
        }

        // ---- MMA phase on buffers s ----
        uint32_t aoff = s * PBUF;
#pragma unroll
        for (int kc = 0; kc < 2; kc++) {
            uint32_t Ah0, Ah1, Ah2, Ah3, Al0, Al1, Al2, Al3;
            LDSM4(Ah0, Ah1, Ah2, Ah3, a_base + aoff + kc * 32);
            LDSM4(Al0, Al1, Al2, Al3, a_base + aoff + OPL + kc * 32);
#pragma unroll
            for (int np = 0; np < 8; np++) {
                uint32_t Bh0, Bh1, Bh2, Bh3, Bl0, Bl1, Bl2, Bl3;
                LDSM4(Bh0, Bh1, Bh2, Bh3, b_base + aoff + np * (16 * 80) + kc * 32);
                LDSM4(Bl0, Bl1, Bl2, Bl3, b_base + aoff + OPL + np * (16 * 80) + kc * 32);
                MMA16816(C[np * 2 + 0], Ah0, Ah1, Ah2, Ah3, Bh0, Bh1);
                MMA16816(C[np * 2 + 0], Ah0, Ah1, Ah2, Ah3, Bl0, Bl1);
                MMA16816(C[np * 2 + 0], Al0, Al1, Al2, Al3, Bh0, Bh1);
                MMA16816(C[np * 2 + 1], Ah0, Ah1, Ah2, Ah3, Bh2, Bh3);
                MMA16816(C[np * 2 + 1], Ah0, Ah1, Ah2, Ah3, Bl2, Bl3);
                MMA16816(C[np * 2 + 1], Al0, Al1, Al2, Al3, Bh2, Bh3);
            }
        }
    }

    l += __shfl_xor_sync(~0u, l, 1);
    float* l_s = (float*)(dyn + OLS);
    if (q == 0) l_s[ti] = l;
    __syncthreads();

    // ---- epilogue: normalize, ELU, store from fragments ----
    {
        int r0 = 16 * w + (lane >> 2);
        int r1 = r0 + 8;
        float inv0 = 1.0f / l_s[r0];
        float inv1 = 1.0f / l_s[r1];
        float* orow0 = out + ((size_t)(b * N_ + ibase + r0)) * H_;
        float* orow1 = out + ((size_t)(b * N_ + ibase + r1)) * H_;
        int hoff = (lane & 3) * 2;
#pragma unroll
        for (int nt = 0; nt < 16; nt++) {
            int h = nt * 8 + hoff;
            float x;
            float2 o;
            x = C[nt][0] * inv0; o.x = x > 0.f ? x : expm1f(x);
            x = C[nt][1] * inv0; o.y = x > 0.f ? x : expm1f(x);
            *(float2*)(orow0 + h) = o;
            x = C[nt][2] * inv1; o.x = x > 0.f ? x : expm1f(x);
            x = C[nt][3] * inv1; o.y = x > 0.f ? x : expm1f(x);
            *(float2*)(orow1 + h) = o;
        }
    }
}

// ---------------------------------------------------------------------------
extern "C" void kernel_launch(void* const* d_in, const int* in_sizes, int n_in,
                              void* d_out, int out_size) {
    const float* inputs = (const float*)d_in[0];
    const int*   adj    = (const int*)d_in[1];
    const float* W      = (const float*)d_in[2];
    const float* bW     = (const float*)d_in[3];
    const float* a      = (const float*)d_in[4];
    const float* b_a    = (const float*)d_in[5];
    float* out = (float*)d_out;

    cudaFuncSetAttribute(k_attn_mma, cudaFuncAttributeMaxDynamicSharedMemorySize, DYNB);

    k_proj<<<(B_ * N_) / 128, 256>>>(inputs, W, bW, a, b_a);
    k_dstmax<<<B_, 256>>>();
    k_attn_mma<<<dim3(N_ / 128, B_), 256, DYNB>>>(adj, out);
}